// round 13
// baseline (speedup 1.0000x reference)
#include <cuda_runtime.h>
#include <math.h>

// ---------------------------------------------------------------------------
// Shapes: B=32, OBS=768, D=512, V=64
// Outputs (float32): h(32*512) pred(32*768) graph(64*64) reasoning(32*512)
//  K1: enc1(T1) + EA + EB + zero(graph)
//  K2: enc2 (T1 -> Z)
//  K3: fused GI GEMM + GRU -> H, HA
//  K4: dec(pred) + rs1(R1) + CC
//  K5: rs2(reasoning) + score (f32x2-packed)
// ---------------------------------------------------------------------------

#define NB 32
#define ND 512
#define NV 64

#define OFF_T1   0          // 32*1024
#define OFF_Z    32768      // 32*512
#define OFF_H    49152      // 32*512
#define OFF_HA   65536      // 32*512
#define OFF_CC   81920      // 32*1024
#define OFF_EA   114688     // 64*1024 (Ea + sc_b1 folded)
#define OFF_EB   180224     // 64*1024
#define OFF_R1   245760     // 32*512
#define SCRATCH_FLOATS 262144

__device__ float g_scratch[SCRATCH_FLOATS];

typedef unsigned long long u64t;

// ---------------------------------------------------------------------------
__device__ __forceinline__ float tanh_approx(float x) {
    float y;
    asm("tanh.approx.f32 %0, %1;" : "=f"(y) : "f"(x));
    return y;
}
__device__ __forceinline__ float sigmoid_acc(float x) {
    return 1.0f / (1.0f + expf(-x));
}
__device__ __forceinline__ float gelu_exact(float x) {
    return 0.5f * x * (1.0f + erff(x * 0.70710678118654752f));
}

// packed f32x2 helpers
__device__ __forceinline__ u64t pk2(float lo, float hi) {
    u64t r; asm("mov.b64 %0, {%1, %2};" : "=l"(r) : "f"(lo), "f"(hi)); return r;
}
__device__ __forceinline__ void upk2(u64t v, float& lo, float& hi) {
    asm("mov.b64 {%0, %1}, %2;" : "=f"(lo), "=f"(hi) : "l"(v));
}
__device__ __forceinline__ u64t addx2(u64t a, u64t b) {
    u64t r; asm("add.rn.f32x2 %0, %1, %2;" : "=l"(r) : "l"(a), "l"(b)); return r;
}
__device__ __forceinline__ u64t mulx2(u64t a, u64t b) {
    u64t r; asm("mul.rn.f32x2 %0, %1, %2;" : "=l"(r) : "l"(a), "l"(b)); return r;
}
__device__ __forceinline__ u64t fmax2(u64t a, u64t b, u64t c) {
    u64t r; asm("fma.rn.f32x2 %0, %1, %2, %3;" : "=l"(r) : "l"(a), "l"(b), "l"(c)); return r;
}

// ---------------------------------------------------------------------------
// Skinny GEMM device fn, explicit 8-deep W load batch.
// ---------------------------------------------------------------------------
template<int MP, int NT, bool GELU>
__device__ __forceinline__ void gemm_dev(
    float* pool, int bid,
    const float* __restrict__ A, int lda,
    const float* __restrict__ W, int ldw, int woff,
    const float* __restrict__ bias,
    float* __restrict__ C, int ldc, int K)
{
    float (*sA)[129] = (float (*)[129])pool;
    const int m  = threadIdx.x % MP;
    const int ns = threadIdx.x / MP;
    const int n  = bid * (NT / MP) + ns;

    float a0 = 0.f, a1 = 0.f, a2 = 0.f, a3 = 0.f;
    const float* wp = W + (size_t)n * ldw + woff;

    for (int k0 = 0; k0 < K; k0 += 128) {
        for (int idx = threadIdx.x; idx < MP * 128; idx += NT) {
            int mm = idx / 128, kk = idx & 127;
            sA[mm][kk] = A[mm * lda + k0 + kk];
        }
        __syncthreads();
        #pragma unroll
        for (int g = 0; g < 4; g++) {
            float4 w[8];
            #pragma unroll
            for (int i = 0; i < 8; i++)
                w[i] = *reinterpret_cast<const float4*>(wp + k0 + g * 32 + i * 4);
            #pragma unroll
            for (int i = 0; i < 8; i++) {
                int kk = g * 32 + i * 4;
                a0 = fmaf(sA[m][kk + 0], w[i].x, a0);
                a1 = fmaf(sA[m][kk + 1], w[i].y, a1);
                a2 = fmaf(sA[m][kk + 2], w[i].z, a2);
                a3 = fmaf(sA[m][kk + 3], w[i].w, a3);
            }
        }
        __syncthreads();
    }
    float v = (a0 + a1) + (a2 + a3);
    if (bias) v += bias[n];
    if (GELU) v = gelu_exact(v);
    C[m * ldc + n] = v;
}

// ---------------------------------------------------------------------------
// K1: enc1 (128 blk) + EA (256 blk) + EB (256 blk) + zero graph (1 blk) = 641
// ---------------------------------------------------------------------------
__global__ void __launch_bounds__(256, 2) k1_kernel(
    const float* __restrict__ obs, const float* __restrict__ enc_w1,
    const float* __restrict__ enc_b1, float* __restrict__ T1,
    const float* __restrict__ embed, const float* __restrict__ sc_w1,
    const float* __restrict__ sc_b1,
    float* __restrict__ EA, float* __restrict__ EB,
    float* __restrict__ graph)
{
    __shared__ float pool[64 * 129];
    int b = blockIdx.x;
    if (b < 128) {
        gemm_dev<32, 256, true >(pool, b,       obs,   768, enc_w1, 768,   0, enc_b1, T1, 1024, 768);
    } else if (b < 384) {
        gemm_dev<64, 256, false>(pool, b - 128, embed, 512, sc_w1, 1536,   0, sc_b1,  EA, 1024, 512);
    } else if (b < 640) {
        gemm_dev<64, 256, false>(pool, b - 384, embed, 512, sc_w1, 1536, 512, nullptr,EB, 1024, 512);
    } else {
        for (int i = threadIdx.x; i < NV * NV; i += 256) graph[i] = 0.0f;
    }
}

// ---------------------------------------------------------------------------
// K2: enc2 (T1 -> Z). 128 blocks x 128 threads.
// ---------------------------------------------------------------------------
__global__ void __launch_bounds__(128, 4) k2_kernel(
    const float* __restrict__ T1, const float* __restrict__ enc_w2,
    const float* __restrict__ enc_b2, float* __restrict__ Z)
{
    __shared__ float pool[32 * 129];
    gemm_dev<32, 128, false>(pool, blockIdx.x, T1, 1024, enc_w2, 1024, 0, enc_b2, Z, 512, 1024);
}

// ---------------------------------------------------------------------------
// K3: fused GI + GRU. 128 blocks x 128 threads. 12 LDG.128 in flight.
// ---------------------------------------------------------------------------
__global__ void __launch_bounds__(128, 4) k3_kernel(
    const float* __restrict__ Z, const float* __restrict__ action,
    const float* __restrict__ gru_wih,
    const float* __restrict__ bih, const float* __restrict__ bhh,
    float* __restrict__ H, float* __restrict__ HA, float* __restrict__ out_h)
{
    __shared__ float sX[32][129];
    const int m  = threadIdx.x % 32;
    const int ns = threadIdx.x / 32;
    const int d  = blockIdx.x * 4 + ns;

    float r0 = 0.f, r1 = 0.f, u0 = 0.f, u1 = 0.f, n0 = 0.f, n1 = 0.f;

    const float* wr = gru_wih + (size_t)(d) * 1024;
    const float* wu = gru_wih + (size_t)(512 + d) * 1024;
    const float* wn = gru_wih + (size_t)(1024 + d) * 1024;

    for (int k0 = 0; k0 < 1024; k0 += 128) {
        const float* src = (k0 < 512) ? (Z + k0) : (action + (k0 - 512));
        for (int idx = threadIdx.x; idx < 32 * 128; idx += 128) {
            int mm = idx >> 7, kk = idx & 127;
            sX[mm][kk] = src[mm * 512 + kk];
        }
        __syncthreads();
        #pragma unroll
        for (int g = 0; g < 8; g++) {
            float4 wr4[4], wu4[4], wn4[4];
            #pragma unroll
            for (int i = 0; i < 4; i++) {
                int kk = k0 + g * 16 + i * 4;
                wr4[i] = *reinterpret_cast<const float4*>(wr + kk);
                wu4[i] = *reinterpret_cast<const float4*>(wu + kk);
                wn4[i] = *reinterpret_cast<const float4*>(wn + kk);
            }
            #pragma unroll
            for (int i = 0; i < 4; i++) {
                int kk = g * 16 + i * 4;
                float x0 = sX[m][kk + 0], x1 = sX[m][kk + 1];
                float x2 = sX[m][kk + 2], x3 = sX[m][kk + 3];
                r0 = fmaf(x0, wr4[i].x, r0);  r1 = fmaf(x1, wr4[i].y, r1);
                r0 = fmaf(x2, wr4[i].z, r0);  r1 = fmaf(x3, wr4[i].w, r1);
                u0 = fmaf(x0, wu4[i].x, u0);  u1 = fmaf(x1, wu4[i].y, u1);
                u0 = fmaf(x2, wu4[i].z, u0);  u1 = fmaf(x3, wu4[i].w, u1);
                n0 = fmaf(x0, wn4[i].x, n0);  n1 = fmaf(x1, wn4[i].y, n1);
                n0 = fmaf(x2, wn4[i].z, n0);  n1 = fmaf(x3, wn4[i].w, n1);
            }
        }
        __syncthreads();
    }

    float r  = sigmoid_acc((r0 + r1) + bih[d]       + bhh[d]);
    float u  = sigmoid_acc((u0 + u1) + bih[512 + d] + bhh[512 + d]);
    float nn = tanhf((n0 + n1) + bih[1024 + d] + r * bhh[1024 + d]);
    float h  = (1.0f - u) * nn;

    int o = m * 512 + d;
    H[o] = h;
    out_h[o] = h;
    HA[o] = h + action[o];
}

// ---------------------------------------------------------------------------
// K4: dec (96 blk) + rs1 (64 blk) + CC (128 blk) = 288 blocks
// ---------------------------------------------------------------------------
__global__ void __launch_bounds__(256, 2) k4_kernel(
    const float* __restrict__ H, const float* __restrict__ HA,
    const float* __restrict__ dec_w, const float* __restrict__ dec_b,
    float* __restrict__ pred,
    const float* __restrict__ rs_w1, const float* __restrict__ rs_b1,
    float* __restrict__ R1,
    const float* __restrict__ sc_w1, float* __restrict__ CC)
{
    __shared__ float pool[32 * 129];
    int b = blockIdx.x;
    if (b < 96) {
        gemm_dev<32, 256, false>(pool, b,       H,  512, dec_w,  512,    0, dec_b,  pred, 768, 512);
    } else if (b < 160) {
        gemm_dev<32, 256, true >(pool, b - 96,  H,  512, rs_w1,  512,    0, rs_b1,  R1,   512, 512);
    } else {
        gemm_dev<32, 256, false>(pool, b - 160, HA, 512, sc_w1, 1536, 1024, nullptr,CC,  1024, 512);
    }
}

// ---------------------------------------------------------------------------
// K5: rs2 (64 blk) + score (128 blk) = 192 blocks
// Score uses packed f32x2: thread owns rows (ra,rb) and j-pair (2*lane, 2*lane+1).
// sE pitch 66 (even -> aligned LDS.64 for the j-pair).
// ---------------------------------------------------------------------------
#define SE_PITCH 66
#define SC_POOL (128*SE_PITCH + 16*128 + 128)   // 10624 floats = 42.5 KB

__global__ void __launch_bounds__(256, 2) k5_kernel(
    const float* __restrict__ R1, const float* __restrict__ rs_w2,
    const float* __restrict__ rs_b2, float* __restrict__ reason,
    const float* __restrict__ EA, const float* __restrict__ EB,
    const float* __restrict__ CC,
    const float* __restrict__ w2, const float* __restrict__ b2p,
    float* __restrict__ graph)
{
    __shared__ float pool[SC_POOL];
    int blk = blockIdx.x;
    if (blk < 64) {
        gemm_dev<32, 256, false>(pool, blk, R1, 512, rs_w2, 512, 0, rs_b2, reason, 512, 512);
        return;
    }
    const int sb = blk - 64;
    const int b  = sb >> 2;
    const int i0 = (sb & 3) * 16;

    float (*sE)[SE_PITCH] = (float (*)[SE_PITCH])pool;            // [dd][j]
    float (*sA)[128] = (float (*)[128])(pool + 128 * SE_PITCH);   // [r][dd]
    float* sW = pool + 128 * SE_PITCH + 16 * 128;

    const int warp = threadIdx.x >> 5;
    const int lane = threadIdx.x & 31;
    const int ra = warp * 2, rb = warp * 2 + 1;
    const int jp = lane * 2;                      // j-pair base

    u64t acc0 = 0, acc1 = 0, lin0 = 0, lin1 = 0;  // packed {j, j+1}

    const float C0 = 0.79788456080286536f;   // sqrt(2/pi)
    const float C1 = 0.03567740813636141f;   // sqrt(2/pi)*0.044715
    const u64t C0x2 = pk2(C0, C0);
    const u64t C1x2 = pk2(C1, C1);

    for (int d0 = 0; d0 < 1024; d0 += 128) {
        for (int idx = threadIdx.x; idx < 64 * 128; idx += 256) {
            int j = idx >> 7, dd = idx & 127;
            sE[dd][j] = EB[j * 1024 + d0 + dd];
        }
        for (int idx = threadIdx.x; idx < 16 * 128; idx += 256) {
            int r = idx >> 7, dd = idx & 127;
            sA[r][dd] = EA[(i0 + r) * 1024 + d0 + dd] + CC[b * 1024 + d0 + dd];
        }
        if (threadIdx.x < 128) sW[threadIdx.x] = 0.5f * w2[d0 + threadIdx.x];
        __syncthreads();

        #pragma unroll 4
        for (int dd = 0; dd < 128; dd++) {
            u64t e2 = *reinterpret_cast<const u64t*>(&sE[dd][jp]);   // LDS.64
            float wv = sW[dd];
            float a0 = sA[ra][dd];
            float a1 = sA[rb][dd];
            u64t wx2v = pk2(wv, wv);
            u64t a0x2 = pk2(a0, a0);
            u64t a1x2 = pk2(a1, a1);

            u64t x0 = addx2(a0x2, e2);
            u64t x1 = addx2(a1x2, e2);

            u64t p0 = fmax2(C1x2, mulx2(x0, x0), C0x2);
            u64t p1 = fmax2(C1x2, mulx2(x1, x1), C0x2);
            u64t t0 = mulx2(x0, p0);
            u64t t1 = mulx2(x1, p1);

            float t0a, t0b, t1a, t1b;
            upk2(t0, t0a, t0b);
            upk2(t1, t1a, t1b);
            u64t h0 = pk2(tanh_approx(t0a), tanh_approx(t0b));
            u64t h1 = pk2(tanh_approx(t1a), tanh_approx(t1b));

            u64t wx0 = mulx2(wx2v, x0);
            u64t wx1 = mulx2(wx2v, x1);

            acc0 = fmax2(wx0, h0, acc0);  lin0 = addx2(lin0, wx0);
            acc1 = fmax2(wx1, h1, acc1);  lin1 = addx2(lin1, wx1);
        }
        __syncthreads();
    }

    const float b2 = b2p[0];
    float a0a, a0b, a1a, a1b, l0a, l0b, l1a, l1b;
    upk2(acc0, a0a, a0b);  upk2(lin0, l0a, l0b);
    upk2(acc1, a1a, a1b);  upk2(lin1, l1a, l1b);

    float s0a = sigmoid_acc(a0a + l0a + b2) * (1.0f / 32.0f);
    float s0b = sigmoid_acc(a0b + l0b + b2) * (1.0f / 32.0f);
    float s1a = sigmoid_acc(a1a + l1a + b2) * (1.0f / 32.0f);
    float s1b = sigmoid_acc(a1b + l1b + b2) * (1.0f / 32.0f);

    atomicAdd(&graph[(i0 + ra) * 64 + jp],     s0a);
    atomicAdd(&graph[(i0 + ra) * 64 + jp + 1], s0b);
    atomicAdd(&graph[(i0 + rb) * 64 + jp],     s1a);
    atomicAdd(&graph[(i0 + rb) * 64 + jp + 1], s1b);
}

// ---------------------------------------------------------------------------
extern "C" void kernel_launch(void* const* d_in, const int* in_sizes, int n_in,
                              void* d_out, int out_size)
{
    float* S = nullptr;
    cudaGetSymbolAddress((void**)&S, g_scratch);

    const float* obs     = (const float*)d_in[0];
    const float* action  = (const float*)d_in[1];
    const float* embed   = (const float*)d_in[2];
    const float* sc_w1   = (const float*)d_in[3];
    const float* sc_b1   = (const float*)d_in[4];
    const float* sc_w2   = (const float*)d_in[5];
    const float* sc_b2   = (const float*)d_in[6];
    const float* enc_w1  = (const float*)d_in[7];
    const float* enc_b1  = (const float*)d_in[8];
    const float* enc_w2  = (const float*)d_in[9];
    const float* enc_b2  = (const float*)d_in[10];
    const float* gru_wih = (const float*)d_in[11];
    // d_in[12] gru_whh unused (h0 == 0)
    const float* gru_bih = (const float*)d_in[13];
    const float* gru_bhh = (const float*)d_in[14];
    const float* dec_w   = (const float*)d_in[15];
    const float* dec_b   = (const float*)d_in[16];
    const float* rs_w1   = (const float*)d_in[17];
    const float* rs_b1   = (const float*)d_in[18];
    const float* rs_w2   = (const float*)d_in[19];
    const float* rs_b2   = (const float*)d_in[20];

    float* out        = (float*)d_out;
    float* out_h      = out;
    float* out_pred   = out + 16384;
    float* out_graph  = out + 16384 + 24576;
    float* out_reason = out + 16384 + 24576 + 4096;

    float* T1 = S + OFF_T1;
    float* Z  = S + OFF_Z;
    float* H  = S + OFF_H;
    float* HA = S + OFF_HA;
    float* CC = S + OFF_CC;
    float* EA = S + OFF_EA;
    float* EB = S + OFF_EB;
    float* R1 = S + OFF_R1;

    k1_kernel<<<641, 256>>>(obs, enc_w1, enc_b1, T1, embed, sc_w1, sc_b1, EA, EB, out_graph);
    k2_kernel<<<128, 128>>>(T1, enc_w2, enc_b2, Z);
    k3_kernel<<<128, 128>>>(Z, action, gru_wih, gru_bih, gru_bhh, H, HA, out_h);
    k4_kernel<<<288, 256>>>(H, HA, dec_w, dec_b, out_pred, rs_w1, rs_b1, R1, sc_w1, CC);
    k5_kernel<<<192, 256>>>(R1, rs_w2, rs_b2, out_reason, EA, EB, CC, sc_w2, sc_b2, out_graph);
}

// round 14
// speedup vs baseline: 1.5175x; 1.5175x over previous
#include <cuda_runtime.h>
#include <math.h>

// ---------------------------------------------------------------------------
// Shapes: B=32, OBS=768, D=512, V=64
// Outputs (float32): h(32*512) pred(32*768) graph(64*64) reasoning(32*512)
// Split-K GEMM scheme: warp = (output column n, K-slice); lanes spread over k
// (coalesced W and A loads), shuffle-fold reduction (lane l -> m=l), smem
// cross-slice reduce. 5 launches:
//  K1: enc1 + EA + EB + zero(graph)      (2561 blocks)
//  K2: enc2 (T1 -> Z)                    (256 blocks)
//  K3: GI GEMM + last-block GRU tail     (768 blocks)
//  K4: dec + rs1 + CC                    (1152 blocks)
//  K5: rs2 + score (scalar, R10 form)    (384 blocks)
// ---------------------------------------------------------------------------

#define NB 32
#define ND 512
#define NV 64

#define OFF_T1   0          // 32*1024
#define OFF_Z    32768      // 32*512
#define OFF_GI   49152      // 32*1536
#define OFF_H    98304      // 32*512
#define OFF_HA   114688     // 32*512
#define OFF_CC   131072     // 32*1024
#define OFF_EA   163840     // 64*1024
#define OFF_EB   229376     // 64*1024
#define OFF_R1   294912     // 32*512
#define SCRATCH_FLOATS 311296

__device__ float g_scratch[SCRATCH_FLOATS];
__device__ int   g_cnt;     // k3 tail counter (reset by tail each launch)

// ---------------------------------------------------------------------------
__device__ __forceinline__ float tanh_approx(float x) {
    float y;
    asm("tanh.approx.f32 %0, %1;" : "=f"(y) : "f"(x));
    return y;
}
__device__ __forceinline__ float sigmoid_acc(float x) {
    return 1.0f / (1.0f + expf(-x));
}
__device__ __forceinline__ float gelu_exact(float x) {
    return 0.5f * x * (1.0f + erff(x * 0.70710678118654752f));
}

// ---------------------------------------------------------------------------
// Split-K warp partial dot: A (pre-offset to slice), lda; wrow (pre-offset to
// slice). Lanes cover k = p + lane*4 (float4). Returns the full-warp slice sum
// for m = lane (after shuffle fold).
// ---------------------------------------------------------------------------
#define FOLD(W, HALF) { \
    _Pragma("unroll") \
    for (int i = 0; i < HALF; i++) { \
        bool hi = (lane & W) != 0; \
        float send = hi ? acc[i] : acc[HALF + i]; \
        float recv = __shfl_xor_sync(0xffffffffu, send, W); \
        acc[i] = (hi ? acc[HALF + i] : acc[i]) + recv; \
    } }

template<int KS>
__device__ __forceinline__ float splitk_warp(
    const float* __restrict__ A, int lda,
    const float* __restrict__ wrow, int lane)
{
    float acc[32];
    #pragma unroll
    for (int i = 0; i < 32; i++) acc[i] = 0.f;

    #pragma unroll
    for (int p = 0; p < KS; p += 128) {
        const int rem = KS - p;                 // 128/256 normally; 64 tail (KS=192)
        const bool on = (lane * 4) < rem;
        const int k = p + lane * 4;
        float4 w4 = on ? *reinterpret_cast<const float4*>(wrow + k)
                       : make_float4(0.f, 0.f, 0.f, 0.f);
        #pragma unroll
        for (int b = 0; b < 4; b++) {
            float4 a4[8];
            #pragma unroll
            for (int i = 0; i < 8; i++) {
                a4[i] = on ? *reinterpret_cast<const float4*>(A + (b * 8 + i) * lda + k)
                           : make_float4(0.f, 0.f, 0.f, 0.f);
            }
            #pragma unroll
            for (int i = 0; i < 8; i++) {
                int m = b * 8 + i;
                acc[m] = fmaf(a4[i].x, w4.x, acc[m]);
                acc[m] = fmaf(a4[i].y, w4.y, acc[m]);
                acc[m] = fmaf(a4[i].z, w4.z, acc[m]);
                acc[m] = fmaf(a4[i].w, w4.w, acc[m]);
            }
        }
    }
    FOLD(16, 16) FOLD(8, 8) FOLD(4, 4) FOLD(2, 2) FOLD(1, 1)
    return acc[0];
}

// ---------------------------------------------------------------------------
// K1: enc1 (512 blk) + EA (1024 blk) + EB (1024 blk) + zero graph (1) = 2561
// enc1: N=1024, K=768 (4 slices of 192); EA/EB: M=64 as 2 row-groups of 32,
// N=1024, K=512 (4 slices of 128).
// ---------------------------------------------------------------------------
__global__ void __launch_bounds__(256) k1_kernel(
    const float* __restrict__ obs, const float* __restrict__ enc_w1,
    const float* __restrict__ enc_b1, float* __restrict__ T1,
    const float* __restrict__ embed, const float* __restrict__ sc_w1,
    const float* __restrict__ sc_b1,
    float* __restrict__ EA, float* __restrict__ EB,
    float* __restrict__ graph)
{
    __shared__ float sP[8 * 33];
    const int bid  = blockIdx.x;
    const int tid  = threadIdx.x;
    const int warp = tid >> 5, lane = tid & 31;
    const int ns = warp >> 2, s = warp & 3;

    if (bid == 2560) {
        for (int i = tid; i < NV * NV; i += 256) graph[i] = 0.0f;
        return;
    }

    float val;
    if (bid < 512) {
        // enc1: n0 = bid*2
        int n = bid * 2 + ns;
        val = splitk_warp<192>(obs + s * 192, 768, enc_w1 + n * 768 + s * 192, lane);
    } else if (bid < 1536) {
        int b2 = bid - 512;
        int mg = b2 & 1;
        int n  = (b2 >> 1) * 2 + ns;
        val = splitk_warp<128>(embed + mg * 32 * 512 + s * 128, 512,
                               sc_w1 + n * 1536 + s * 128, lane);
    } else {
        int b2 = bid - 1536;
        int mg = b2 & 1;
        int n  = (b2 >> 1) * 2 + ns;
        val = splitk_warp<128>(embed + mg * 32 * 512 + s * 128, 512,
                               sc_w1 + n * 1536 + 512 + s * 128, lane);
    }
    sP[warp * 33 + lane] = val;
    __syncthreads();
    if (tid < 64) {
        int m = tid & 31, nn = tid >> 5;
        float v = sP[(nn * 4 + 0) * 33 + m] + sP[(nn * 4 + 1) * 33 + m]
                + sP[(nn * 4 + 2) * 33 + m] + sP[(nn * 4 + 3) * 33 + m];
        if (bid < 512) {
            int n = bid * 2 + nn;
            T1[m * 1024 + n] = gelu_exact(v + enc_b1[n]);
        } else if (bid < 1536) {
            int b2 = bid - 512;
            int mg = b2 & 1;
            int n  = (b2 >> 1) * 2 + nn;
            EA[(mg * 32 + m) * 1024 + n] = v + sc_b1[n];
        } else {
            int b2 = bid - 1536;
            int mg = b2 & 1;
            int n  = (b2 >> 1) * 2 + nn;
            EB[(mg * 32 + m) * 1024 + n] = v;
        }
    }
}

// ---------------------------------------------------------------------------
// K2: enc2 (T1 -> Z). N=512, K=1024 (4 slices of 256). 256 blocks.
// ---------------------------------------------------------------------------
__global__ void __launch_bounds__(256) k2_kernel(
    const float* __restrict__ T1, const float* __restrict__ enc_w2,
    const float* __restrict__ enc_b2, float* __restrict__ Z)
{
    __shared__ float sP[8 * 33];
    const int tid = threadIdx.x;
    const int warp = tid >> 5, lane = tid & 31;
    const int ns = warp >> 2, s = warp & 3;
    int n = blockIdx.x * 2 + ns;

    float val = splitk_warp<256>(T1 + s * 256, 1024, enc_w2 + n * 1024 + s * 256, lane);
    sP[warp * 33 + lane] = val;
    __syncthreads();
    if (tid < 64) {
        int m = tid & 31, nn = tid >> 5;
        float v = sP[(nn * 4 + 0) * 33 + m] + sP[(nn * 4 + 1) * 33 + m]
                + sP[(nn * 4 + 2) * 33 + m] + sP[(nn * 4 + 3) * 33 + m];
        int n2 = blockIdx.x * 2 + nn;
        Z[m * 512 + n2] = v + enc_b2[n2];
    }
}

// ---------------------------------------------------------------------------
// K3: GI = [Z|action] @ wih^T + bih. N=1536, K=1024 (slices: 2 in Z, 2 in
// action). 768 blocks. Last block (atomic counter) applies the GRU pointwise:
// h0=0 => gh=bhh, h=(1-u)*n. Writes H, HA, out_h; resets counter.
// ---------------------------------------------------------------------------
__global__ void __launch_bounds__(256) k3_kernel(
    const float* __restrict__ Z, const float* __restrict__ action,
    const float* __restrict__ gru_wih,
    const float* __restrict__ bih, const float* __restrict__ bhh,
    float* __restrict__ GI,
    float* __restrict__ H, float* __restrict__ HA, float* __restrict__ out_h)
{
    __shared__ float sP[8 * 33];
    __shared__ int sLast;
    const int tid = threadIdx.x;
    const int warp = tid >> 5, lane = tid & 31;
    const int ns = warp >> 2, s = warp & 3;
    int n = blockIdx.x * 2 + ns;

    const float* Asl = (s < 2) ? (Z + s * 256) : (action + (s - 2) * 256);
    float val = splitk_warp<256>(Asl, 512, gru_wih + n * 1024 + s * 256, lane);
    sP[warp * 33 + lane] = val;
    __syncthreads();
    if (tid < 64) {
        int m = tid & 31, nn = tid >> 5;
        float v = sP[(nn * 4 + 0) * 33 + m] + sP[(nn * 4 + 1) * 33 + m]
                + sP[(nn * 4 + 2) * 33 + m] + sP[(nn * 4 + 3) * 33 + m];
        int n2 = blockIdx.x * 2 + nn;
        GI[m * 1536 + n2] = v + bih[n2];
    }
    __syncthreads();
    if (tid == 0) {
        __threadfence();
        int old = atomicAdd(&g_cnt, 1);
        sLast = (old == (int)gridDim.x - 1) ? 1 : 0;
    }
    __syncthreads();
    if (sLast) {
        __threadfence();
        for (int i = tid; i < NB * ND; i += 256) {
            int b = i >> 9, d = i & 511;
            const float* gi = GI + b * 1536;
            float r  = sigmoid_acc(gi[d]        + bhh[d]);
            float u  = sigmoid_acc(gi[512 + d]  + bhh[512 + d]);
            float nn = tanhf(gi[1024 + d] + r * bhh[1024 + d]);
            float h  = (1.0f - u) * nn;
            H[i] = h;
            out_h[i] = h;
            HA[i] = h + action[i];
        }
        if (tid == 0) g_cnt = 0;
    }
}

// ---------------------------------------------------------------------------
// K4: dec (384 blk) + rs1 (256 blk) + CC (512 blk) = 1152. K=512, slice 128.
// ---------------------------------------------------------------------------
__global__ void __launch_bounds__(256) k4_kernel(
    const float* __restrict__ H, const float* __restrict__ HA,
    const float* __restrict__ dec_w, const float* __restrict__ dec_b,
    float* __restrict__ pred,
    const float* __restrict__ rs_w1, const float* __restrict__ rs_b1,
    float* __restrict__ R1,
    const float* __restrict__ sc_w1, float* __restrict__ CC)
{
    __shared__ float sP[8 * 33];
    const int bid = blockIdx.x;
    const int tid = threadIdx.x;
    const int warp = tid >> 5, lane = tid & 31;
    const int ns = warp >> 2, s = warp & 3;

    float val;
    if (bid < 384) {
        int n = bid * 2 + ns;
        val = splitk_warp<128>(H + s * 128, 512, dec_w + n * 512 + s * 128, lane);
    } else if (bid < 640) {
        int n = (bid - 384) * 2 + ns;
        val = splitk_warp<128>(H + s * 128, 512, rs_w1 + n * 512 + s * 128, lane);
    } else {
        int n = (bid - 640) * 2 + ns;
        val = splitk_warp<128>(HA + s * 128, 512, sc_w1 + n * 1536 + 1024 + s * 128, lane);
    }
    sP[warp * 33 + lane] = val;
    __syncthreads();
    if (tid < 64) {
        int m = tid & 31, nn = tid >> 5;
        float v = sP[(nn * 4 + 0) * 33 + m] + sP[(nn * 4 + 1) * 33 + m]
                + sP[(nn * 4 + 2) * 33 + m] + sP[(nn * 4 + 3) * 33 + m];
        if (bid < 384) {
            int n = bid * 2 + nn;
            pred[m * 768 + n] = v + dec_b[n];
        } else if (bid < 640) {
            int n = (bid - 384) * 2 + nn;
            R1[m * 512 + n] = gelu_exact(v + rs_b1[n]);
        } else {
            int n = (bid - 640) * 2 + nn;
            CC[m * 1024 + n] = v;
        }
    }
}

// ---------------------------------------------------------------------------
// K5: rs2 (256 blk, split-K) + score (128 blk, scalar R10 form) = 384 blocks
// Score: graph[i,j] += (1/32)*sigmoid( sum_d w2*gelu(x) + b2 ),
//   x = CC[b,d]+EA[i,d]+EB[j,d]; gelu(x) ~ 0.5x + 0.5x*tanh(t(x)).
// Block: fixed b, 16 i-rows, all 64 j. 8 warps x 2 rows; lane does j, j+32.
// ---------------------------------------------------------------------------
#define SC_POOL (128*65 + 16*128 + 128)    // 10576 floats

__global__ void __launch_bounds__(256) k5_kernel(
    const float* __restrict__ R1, const float* __restrict__ rs_w2,
    const float* __restrict__ rs_b2, float* __restrict__ reason,
    const float* __restrict__ EA, const float* __restrict__ EB,
    const float* __restrict__ CC,
    const float* __restrict__ w2, const float* __restrict__ b2p,
    float* __restrict__ graph)
{
    __shared__ float pool[SC_POOL];
    const int blk = blockIdx.x;
    const int tid = threadIdx.x;
    const int warp = tid >> 5;
    const int lane = tid & 31;

    if (blk < 256) {
        // rs2 split-K
        const int ns = warp >> 2, s = warp & 3;
        int n = blk * 2 + ns;
        float val = splitk_warp<128>(R1 + s * 128, 512, rs_w2 + n * 512 + s * 128, lane);
        pool[warp * 33 + lane] = val;
        __syncthreads();
        if (tid < 64) {
            int m = tid & 31, nn = tid >> 5;
            float v = pool[(nn * 4 + 0) * 33 + m] + pool[(nn * 4 + 1) * 33 + m]
                    + pool[(nn * 4 + 2) * 33 + m] + pool[(nn * 4 + 3) * 33 + m];
            int n2 = blk * 2 + nn;
            reason[m * 512 + n2] = v + rs_b2[n2];
        }
        return;
    }

    const int sb = blk - 256;             // 0..127
    const int b  = sb >> 2;               // batch
    const int i0 = (sb & 3) * 16;         // i-row block

    float (*sE)[65]  = (float (*)[65])pool;                 // [dd][j]
    float (*sA)[128] = (float (*)[128])(pool + 128 * 65);   // [r][dd]
    float* sW = pool + 128 * 65 + 16 * 128;

    const int ra = warp * 2, rb = warp * 2 + 1;

    float acc0a = 0.f, acc0b = 0.f, acc1a = 0.f, acc1b = 0.f;
    float lin0a = 0.f, lin0b = 0.f, lin1a = 0.f, lin1b = 0.f;

    const float C0 = 0.79788456080286536f;   // sqrt(2/pi)
    const float C1 = 0.03567740813636141f;   // sqrt(2/pi)*0.044715

    for (int d0 = 0; d0 < 1024; d0 += 128) {
        for (int idx = tid; idx < 64 * 128; idx += 256) {
            int j = idx >> 7, dd = idx & 127;
            sE[dd][j] = EB[j * 1024 + d0 + dd];
        }
        for (int idx = tid; idx < 16 * 128; idx += 256) {
            int r = idx >> 7, dd = idx & 127;
            sA[r][dd] = EA[(i0 + r) * 1024 + d0 + dd] + CC[b * 1024 + d0 + dd];
        }
        if (tid < 128) sW[tid] = 0.5f * w2[d0 + tid];
        __syncthreads();

        #pragma unroll 4
        for (int dd = 0; dd < 128; dd++) {
            float ea = sE[dd][lane];
            float eb = sE[dd][lane + 32];
            float w  = sW[dd];
            float a0 = sA[ra][dd];
            float a1 = sA[rb][dd];

            float x0a = a0 + ea, x0b = a0 + eb;
            float x1a = a1 + ea, x1b = a1 + eb;

            float t0a = x0a * fmaf(C1, x0a * x0a, C0);
            float t0b = x0b * fmaf(C1, x0b * x0b, C0);
            float t1a = x1a * fmaf(C1, x1a * x1a, C0);
            float t1b = x1b * fmaf(C1, x1b * x1b, C0);

            float h0a = tanh_approx(t0a);
            float h0b = tanh_approx(t0b);
            float h1a = tanh_approx(t1a);
            float h1b = tanh_approx(t1b);

            float wx0a = w * x0a, wx0b = w * x0b;
            float wx1a = w * x1a, wx1b = w * x1b;

            acc0a = fmaf(wx0a, h0a, acc0a);  lin0a += wx0a;
            acc0b = fmaf(wx0b, h0b, acc0b);  lin0b += wx0b;
            acc1a = fmaf(wx1a, h1a, acc1a);  lin1a += wx1a;
            acc1b = fmaf(wx1b, h1b, acc1b);  lin1b += wx1b;
        }
        __syncthreads();
    }

    const float b2 = b2p[0];
    float s0a = sigmoid_acc(acc0a + lin0a + b2) * (1.0f / 32.0f);
    float s0b = sigmoid_acc(acc0b + lin0b + b2) * (1.0f / 32.0f);
    float s1a = sigmoid_acc(acc1a + lin1a + b2) * (1.0f / 32.0f);
    float s1b = sigmoid_acc(acc1b + lin1b + b2) * (1.0f / 32.0f);

    atomicAdd(&graph[(i0 + ra) * 64 + lane],      s0a);
    atomicAdd(&graph[(i0 + ra) * 64 + lane + 32], s0b);
    atomicAdd(&graph[(i0 + rb) * 64 + lane],      s1a);
    atomicAdd(&graph[(i0 + rb) * 64 + lane + 32], s1b);
}

// ---------------------------------------------------------------------------
extern "C" void kernel_launch(void* const* d_in, const int* in_sizes, int n_in,
                              void* d_out, int out_size)
{
    float* S = nullptr;
    cudaGetSymbolAddress((void**)&S, g_scratch);

    const float* obs     = (const float*)d_in[0];
    const float* action  = (const float*)d_in[1];
    const float* embed   = (const float*)d_in[2];
    const float* sc_w1   = (const float*)d_in[3];
    const float* sc_b1   = (const float*)d_in[4];
    const float* sc_w2   = (const float*)d_in[5];
    const float* sc_b2   = (const float*)d_in[6];
    const float* enc_w1  = (const float*)d_in[7];
    const float* enc_b1  = (const float*)d_in[8];
    const float* enc_w2  = (const float*)d_in[9];
    const float* enc_b2  = (const float*)d_in[10];
    const float* gru_wih = (const float*)d_in[11];
    // d_in[12] gru_whh unused (h0 == 0)
    const float* gru_bih = (const float*)d_in[13];
    const float* gru_bhh = (const float*)d_in[14];
    const float* dec_w   = (const float*)d_in[15];
    const float* dec_b   = (const float*)d_in[16];
    const float* rs_w1   = (const float*)d_in[17];
    const float* rs_b1   = (const float*)d_in[18];
    const float* rs_w2   = (const float*)d_in[19];
    const float* rs_b2   = (const float*)d_in[20];

    float* out        = (float*)d_out;
    float* out_h      = out;
    float* out_pred   = out + 16384;
    float* out_graph  = out + 16384 + 24576;
    float* out_reason = out + 16384 + 24576 + 4096;

    float* T1 = S + OFF_T1;
    float* Z  = S + OFF_Z;
    float* GI = S + OFF_GI;
    float* H  = S + OFF_H;
    float* HA = S + OFF_HA;
    float* CC = S + OFF_CC;
    float* EA = S + OFF_EA;
    float* EB = S + OFF_EB;
    float* R1 = S + OFF_R1;

    k1_kernel<<<2561, 256>>>(obs, enc_w1, enc_b1, T1, embed, sc_w1, sc_b1, EA, EB, out_graph);
    k2_kernel<<<256, 256>>>(T1, enc_w2, enc_b2, Z);
    k3_kernel<<<768, 256>>>(Z, action, gru_wih, gru_bih, gru_bhh, GI, H, HA, out_h);
    k4_kernel<<<1152, 256>>>(H, HA, dec_w, dec_b, out_pred, rs_w1, rs_b1, R1, sc_w1, CC);
    k5_kernel<<<384, 256>>>(R1, rs_w2, rs_b2, out_reason, EA, EB, CC, sc_w2, sc_b2, out_graph);
}

// round 15
// speedup vs baseline: 2.1707x; 1.4304x over previous
#include <cuda_runtime.h>
#include <math.h>

// ---------------------------------------------------------------------------
// Shapes: B=32, OBS=768, D=512, V=64
// Outputs (float32): h(32*512) pred(32*768) graph(64*64) reasoning(32*512)
//
// SINGLE persistent kernel, 296 blocks (2/SM x 148) x 256 threads.
// Phases separated by device grid barrier (monotonic counters, replay-safe):
//  P0: enc1(T1) + EA + EB + zero(graph)   (2561 units)
//  P1: enc2 -> Z                          (256 units)
//  P2: GI = [Z|action] @ wih^T + bih      (768 units)
//  P3: GRU pointwise -> H, HA, out_h
//  P4: dec(pred) + rs1(R1) + CC           (1152 units)
//  P5: score (256 units of 8 i-rows) + rs2 (256 units)
// GEMM units use the R14 split-K scheme: warp = (n, K-slice), lanes spread
// over k (coalesced), shuffle-fold (lane -> m), smem cross-slice reduce.
// ---------------------------------------------------------------------------

#define NB 32
#define ND 512
#define NV 64
#define NBLK 296

#define OFF_T1   0          // 32*1024
#define OFF_Z    32768      // 32*512
#define OFF_GI   49152      // 32*1536
#define OFF_H    98304      // 32*512
#define OFF_HA   114688     // 32*512
#define OFF_CC   131072     // 32*1024
#define OFF_EA   163840     // 64*1024
#define OFF_EB   229376     // 64*1024
#define OFF_R1   294912     // 32*512
#define SCRATCH_FLOATS 311296

__device__ float g_scratch[SCRATCH_FLOATS];
__device__ int   g_bars[8];   // monotonic grid-barrier counters (never reset)

// ---------------------------------------------------------------------------
__device__ __forceinline__ float tanh_approx(float x) {
    float y;
    asm("tanh.approx.f32 %0, %1;" : "=f"(y) : "f"(x));
    return y;
}
__device__ __forceinline__ float sigmoid_acc(float x) {
    return 1.0f / (1.0f + expf(-x));
}
__device__ __forceinline__ float gelu_exact(float x) {
    return 0.5f * x * (1.0f + erff(x * 0.70710678118654752f));
}

// Monotonic grid barrier: works across graph replays without reset because
// each launch adds exactly NBLK to counter i; a block waits for its own
// launch's round to complete.
__device__ __forceinline__ void grid_sync(int i) {
    __syncthreads();
    if (threadIdx.x == 0) {
        __threadfence();
        int old = atomicAdd(&g_bars[i], 1);
        int target = old - (old % NBLK) + NBLK;
        while (*((volatile int*)&g_bars[i]) < target) __nanosleep(64);
        __threadfence();
    }
    __syncthreads();
}

// ---------------------------------------------------------------------------
// Split-K warp partial dot (R14): lanes cover k = p + lane*4 (float4);
// returns full slice sum for m = lane after shuffle fold.
// ---------------------------------------------------------------------------
#define FOLD(W, HALF) { \
    _Pragma("unroll") \
    for (int i = 0; i < HALF; i++) { \
        bool hi = (lane & W) != 0; \
        float send = hi ? acc[i] : acc[HALF + i]; \
        float recv = __shfl_xor_sync(0xffffffffu, send, W); \
        acc[i] = (hi ? acc[HALF + i] : acc[i]) + recv; \
    } }

template<int KS>
__device__ __forceinline__ float splitk_warp(
    const float* __restrict__ A, int lda,
    const float* __restrict__ wrow, int lane)
{
    float acc[32];
    #pragma unroll
    for (int i = 0; i < 32; i++) acc[i] = 0.f;

    #pragma unroll
    for (int p = 0; p < KS; p += 128) {
        const int rem = KS - p;
        const bool on = (lane * 4) < rem;
        const int k = p + lane * 4;
        float4 w4 = on ? *reinterpret_cast<const float4*>(wrow + k)
                       : make_float4(0.f, 0.f, 0.f, 0.f);
        #pragma unroll
        for (int b = 0; b < 4; b++) {
            float4 a4[8];
            #pragma unroll
            for (int i = 0; i < 8; i++) {
                a4[i] = on ? *reinterpret_cast<const float4*>(A + (b * 8 + i) * lda + k)
                           : make_float4(0.f, 0.f, 0.f, 0.f);
            }
            #pragma unroll
            for (int i = 0; i < 8; i++) {
                int m = b * 8 + i;
                acc[m] = fmaf(a4[i].x, w4.x, acc[m]);
                acc[m] = fmaf(a4[i].y, w4.y, acc[m]);
                acc[m] = fmaf(a4[i].z, w4.z, acc[m]);
                acc[m] = fmaf(a4[i].w, w4.w, acc[m]);
            }
        }
    }
    FOLD(16, 16) FOLD(8, 8) FOLD(4, 4) FOLD(2, 2) FOLD(1, 1)
    return acc[0];
}

// smem pool: score needs 128*65 + 8*128 + 128 = 9472 floats (37.9 KB)
#define POOL_FLOATS (128*65 + 8*128 + 128)

// ---------------------------------------------------------------------------
__global__ void __launch_bounds__(256, 2) mega_kernel(
    const float* __restrict__ obs, const float* __restrict__ action,
    const float* __restrict__ embed,
    const float* __restrict__ sc_w1, const float* __restrict__ sc_b1,
    const float* __restrict__ sc_w2, const float* __restrict__ sc_b2,
    const float* __restrict__ enc_w1, const float* __restrict__ enc_b1,
    const float* __restrict__ enc_w2, const float* __restrict__ enc_b2,
    const float* __restrict__ gru_wih, const float* __restrict__ gru_bih,
    const float* __restrict__ gru_bhh,
    const float* __restrict__ dec_w, const float* __restrict__ dec_b,
    const float* __restrict__ rs_w1, const float* __restrict__ rs_b1,
    const float* __restrict__ rs_w2, const float* __restrict__ rs_b2,
    float* __restrict__ T1, float* __restrict__ Z, float* __restrict__ GI,
    float* __restrict__ H, float* __restrict__ HA, float* __restrict__ CC,
    float* __restrict__ EA, float* __restrict__ EB, float* __restrict__ R1,
    float* __restrict__ out_h, float* __restrict__ out_pred,
    float* __restrict__ out_graph, float* __restrict__ out_reason)
{
    __shared__ float pool[POOL_FLOATS];
    const int bid  = blockIdx.x;
    const int tid  = threadIdx.x;
    const int warp = tid >> 5, lane = tid & 31;
    const int ns = warp >> 2, s = warp & 3;     // for GEMM units: n-sub, slice

    // ---------------- P0: enc1 (512) + EA (1024) + EB (1024) + zero (1) ----
    for (int u = bid; u < 2561; u += NBLK) {
        if (u == 2560) {
            for (int i = tid; i < NV * NV; i += 256) out_graph[i] = 0.0f;
            continue;
        }
        float val;
        if (u < 512) {
            int n = u * 2 + ns;
            val = splitk_warp<192>(obs + s * 192, 768, enc_w1 + n * 768 + s * 192, lane);
        } else if (u < 1536) {
            int b2 = u - 512;
            int mg = b2 & 1;
            int n  = (b2 >> 1) * 2 + ns;
            val = splitk_warp<128>(embed + mg * 32 * 512 + s * 128, 512,
                                   sc_w1 + n * 1536 + s * 128, lane);
        } else {
            int b2 = u - 1536;
            int mg = b2 & 1;
            int n  = (b2 >> 1) * 2 + ns;
            val = splitk_warp<128>(embed + mg * 32 * 512 + s * 128, 512,
                                   sc_w1 + n * 1536 + 512 + s * 128, lane);
        }
        pool[warp * 33 + lane] = val;
        __syncthreads();
        if (tid < 64) {
            int m = tid & 31, nn = tid >> 5;
            float v = pool[(nn * 4 + 0) * 33 + m] + pool[(nn * 4 + 1) * 33 + m]
                    + pool[(nn * 4 + 2) * 33 + m] + pool[(nn * 4 + 3) * 33 + m];
            if (u < 512) {
                int n = u * 2 + nn;
                T1[m * 1024 + n] = gelu_exact(v + enc_b1[n]);
            } else if (u < 1536) {
                int b2 = u - 512;
                int mg = b2 & 1;
                int n  = (b2 >> 1) * 2 + nn;
                EA[(mg * 32 + m) * 1024 + n] = v + sc_b1[n];
            } else {
                int b2 = u - 1536;
                int mg = b2 & 1;
                int n  = (b2 >> 1) * 2 + nn;
                EB[(mg * 32 + m) * 1024 + n] = v;
            }
        }
        __syncthreads();
    }
    grid_sync(0);

    // ---------------- P1: enc2 -> Z (256 units) ----------------------------
    for (int u = bid; u < 256; u += NBLK) {
        int n = u * 2 + ns;
        float val = splitk_warp<256>(T1 + s * 256, 1024, enc_w2 + n * 1024 + s * 256, lane);
        pool[warp * 33 + lane] = val;
        __syncthreads();
        if (tid < 64) {
            int m = tid & 31, nn = tid >> 5;
            float v = pool[(nn * 4 + 0) * 33 + m] + pool[(nn * 4 + 1) * 33 + m]
                    + pool[(nn * 4 + 2) * 33 + m] + pool[(nn * 4 + 3) * 33 + m];
            int n2 = u * 2 + nn;
            Z[m * 512 + n2] = v + enc_b2[n2];
        }
        __syncthreads();
    }
    grid_sync(1);

    // ---------------- P2: GI (768 units) -----------------------------------
    for (int u = bid; u < 768; u += NBLK) {
        int n = u * 2 + ns;
        const float* Asl = (s < 2) ? (Z + s * 256) : (action + (s - 2) * 256);
        float val = splitk_warp<256>(Asl, 512, gru_wih + n * 1024 + s * 256, lane);
        pool[warp * 33 + lane] = val;
        __syncthreads();
        if (tid < 64) {
            int m = tid & 31, nn = tid >> 5;
            float v = pool[(nn * 4 + 0) * 33 + m] + pool[(nn * 4 + 1) * 33 + m]
                    + pool[(nn * 4 + 2) * 33 + m] + pool[(nn * 4 + 3) * 33 + m];
            int n2 = u * 2 + nn;
            GI[m * 1536 + n2] = v + gru_bih[n2];
        }
        __syncthreads();
    }
    grid_sync(2);

    // ---------------- P3: GRU pointwise (h0=0 => gh=bhh, h=(1-u)*n) --------
    {
        int i = bid * 256 + tid;
        if (i < NB * ND) {
            int b = i >> 9, d = i & 511;
            const float* gi = GI + b * 1536;
            float r  = sigmoid_acc(gi[d]        + gru_bhh[d]);
            float uu = sigmoid_acc(gi[512 + d]  + gru_bhh[512 + d]);
            float nn = tanhf(gi[1024 + d] + r * gru_bhh[1024 + d]);
            float h  = (1.0f - uu) * nn;
            H[i] = h;
            out_h[i] = h;
            HA[i] = h + action[i];
        }
    }
    grid_sync(3);

    // ---------------- P4: dec (384) + rs1 (256) + CC (512) = 1152 ----------
    for (int u = bid; u < 1152; u += NBLK) {
        float val;
        if (u < 384) {
            int n = u * 2 + ns;
            val = splitk_warp<128>(H + s * 128, 512, dec_w + n * 512 + s * 128, lane);
        } else if (u < 640) {
            int n = (u - 384) * 2 + ns;
            val = splitk_warp<128>(H + s * 128, 512, rs_w1 + n * 512 + s * 128, lane);
        } else {
            int n = (u - 640) * 2 + ns;
            val = splitk_warp<128>(HA + s * 128, 512, sc_w1 + n * 1536 + 1024 + s * 128, lane);
        }
        pool[warp * 33 + lane] = val;
        __syncthreads();
        if (tid < 64) {
            int m = tid & 31, nn = tid >> 5;
            float v = pool[(nn * 4 + 0) * 33 + m] + pool[(nn * 4 + 1) * 33 + m]
                    + pool[(nn * 4 + 2) * 33 + m] + pool[(nn * 4 + 3) * 33 + m];
            if (u < 384) {
                int n = u * 2 + nn;
                out_pred[m * 768 + n] = v + dec_b[n];
            } else if (u < 640) {
                int n = (u - 384) * 2 + nn;
                R1[m * 512 + n] = gelu_exact(v + rs_b1[n]);
            } else {
                int n = (u - 640) * 2 + nn;
                CC[m * 1024 + n] = v;
            }
        }
        __syncthreads();
    }
    grid_sync(4);

    // ---------------- P5: score (256 units, 8 rows) + rs2 (256 units) ------
    // score unit u<256: b = u>>3, i0 = (u&7)*8. warp -> one i-row; lane does
    // j = lane and j+32. logit = sum_d 0.5*w2*x*(1+tanh(t(x))) + b2.
    float (*sE)[65] = (float (*)[65])pool;                 // [dd][j] 128x65
    float (*sA8)    = pool + 128 * 65;                     // [8][128]
    float* sW       = pool + 128 * 65 + 8 * 128;

    const float C0 = 0.79788456080286536f;   // sqrt(2/pi)
    const float C1 = 0.03567740813636141f;   // sqrt(2/pi)*0.044715

    for (int u = bid; u < 512; u += NBLK) {
        if (u < 256) {
            const int b  = u >> 3;
            const int i0 = (u & 7) * 8;
            const int row = i0 + warp;

            float acca = 0.f, accb = 0.f, lina = 0.f, linb = 0.f;

            for (int d0 = 0; d0 < 1024; d0 += 128) {
                for (int idx = tid; idx < 64 * 128; idx += 256) {
                    int j = idx >> 7, dd = idx & 127;
                    sE[dd][j] = EB[j * 1024 + d0 + dd];
                }
                for (int idx = tid; idx < 8 * 128; idx += 256) {
                    int r = idx >> 7, dd = idx & 127;
                    sA8[r * 128 + dd] = EA[(i0 + r) * 1024 + d0 + dd] + CC[b * 1024 + d0 + dd];
                }
                if (tid < 128) sW[tid] = 0.5f * sc_w2[d0 + tid];
                __syncthreads();

                #pragma unroll 4
                for (int dd = 0; dd < 128; dd++) {
                    float ea = sE[dd][lane];
                    float eb = sE[dd][lane + 32];
                    float w  = sW[dd];
                    float a  = sA8[warp * 128 + dd];

                    float xa = a + ea, xb = a + eb;
                    float ta = xa * fmaf(C1, xa * xa, C0);
                    float tb = xb * fmaf(C1, xb * xb, C0);
                    float ha = tanh_approx(ta);
                    float hb = tanh_approx(tb);
                    float wxa = w * xa, wxb = w * xb;
                    acca = fmaf(wxa, ha, acca);  lina += wxa;
                    accb = fmaf(wxb, hb, accb);  linb += wxb;
                }
                __syncthreads();
            }

            const float b2 = sc_b2[0];
            float sa = sigmoid_acc(acca + lina + b2) * (1.0f / 32.0f);
            float sb = sigmoid_acc(accb + linb + b2) * (1.0f / 32.0f);
            atomicAdd(&out_graph[row * 64 + lane],      sa);
            atomicAdd(&out_graph[row * 64 + lane + 32], sb);
        } else {
            // rs2 unit
            int n = (u - 256) * 2 + ns;
            float val = splitk_warp<128>(R1 + s * 128, 512, rs_w2 + n * 512 + s * 128, lane);
            pool[warp * 33 + lane] = val;
            __syncthreads();
            if (tid < 64) {
                int m = tid & 31, nn = tid >> 5;
                float v = pool[(nn * 4 + 0) * 33 + m] + pool[(nn * 4 + 1) * 33 + m]
                        + pool[(nn * 4 + 2) * 33 + m] + pool[(nn * 4 + 3) * 33 + m];
                int n2 = (u - 256) * 2 + nn;
                out_reason[m * 512 + n2] = v + rs_b2[n2];
            }
            __syncthreads();
        }
    }
}

// ---------------------------------------------------------------------------
extern "C" void kernel_launch(void* const* d_in, const int* in_sizes, int n_in,
                              void* d_out, int out_size)
{
    float* S = nullptr;
    cudaGetSymbolAddress((void**)&S, g_scratch);

    const float* obs     = (const float*)d_in[0];
    const float* action  = (const float*)d_in[1];
    const float* embed   = (const float*)d_in[2];
    const float* sc_w1   = (const float*)d_in[3];
    const float* sc_b1   = (const float*)d_in[4];
    const float* sc_w2   = (const float*)d_in[5];
    const float* sc_b2   = (const float*)d_in[6];
    const float* enc_w1  = (const float*)d_in[7];
    const float* enc_b1  = (const float*)d_in[8];
    const float* enc_w2  = (const float*)d_in[9];
    const float* enc_b2  = (const float*)d_in[10];
    const float* gru_wih = (const float*)d_in[11];
    // d_in[12] gru_whh unused (h0 == 0)
    const float* gru_bih = (const float*)d_in[13];
    const float* gru_bhh = (const float*)d_in[14];
    const float* dec_w   = (const float*)d_in[15];
    const float* dec_b   = (const float*)d_in[16];
    const float* rs_w1   = (const float*)d_in[17];
    const float* rs_b1   = (const float*)d_in[18];
    const float* rs_w2   = (const float*)d_in[19];
    const float* rs_b2   = (const float*)d_in[20];

    float* out        = (float*)d_out;
    float* out_h      = out;
    float* out_pred   = out + 16384;
    float* out_graph  = out + 16384 + 24576;
    float* out_reason = out + 16384 + 24576 + 4096;

    float* T1 = S + OFF_T1;
    float* Z  = S + OFF_Z;
    float* GI = S + OFF_GI;
    float* H  = S + OFF_H;
    float* HA = S + OFF_HA;
    float* CC = S + OFF_CC;
    float* EA = S + OFF_EA;
    float* EB = S + OFF_EB;
    float* R1 = S + OFF_R1;

    mega_kernel<<<NBLK, 256>>>(
        obs, action, embed,
        sc_w1, sc_b1, sc_w2, sc_b2,
        enc_w1, enc_b1, enc_w2, enc_b2,
        gru_wih, gru_bih, gru_bhh,
        dec_w, dec_b, rs_w1, rs_b1, rs_w2, rs_b2,
        T1, Z, GI, H, HA, CC, EA, EB, R1,
        out_h, out_pred, out_graph, out_reason);
}